// round 4
// baseline (speedup 1.0000x reference)
#include <cuda_runtime.h>

// GRU: B=256, T=2048, I=10, H=64. PyTorch gate order (r, z, n).
// grid=128 CTAs x 256 threads = 2 streams (1 batch each) x 128 threads.
// Lane pair (2u, 2u+1) owns hidden unit u and computes ALL gates (r,z,n),
// each lane summing half the k-range; halves merge via shfl.bfly (no barrier).
// Single named barrier per timestep (double-buffered h publish).
// gi = W_ih.x + biases precomputed per 32-step chunk into shared.

#define B_    256
#define T_    2048
#define I_    10
#define H_    64
#define CHUNK 32
#define TPB   256
#define STPB  128

typedef unsigned long long ull;

__device__ __forceinline__ ull ffma2(ull a, ull b, ull c) {
    ull d;
    asm("fma.rn.f32x2 %0, %1, %2, %3;" : "=l"(d) : "l"(a), "l"(b), "l"(c));
    return d;
}
__device__ __forceinline__ ull fadd2(ull a, ull b) {
    ull d;
    asm("add.rn.f32x2 %0, %1, %2;" : "=l"(d) : "l"(a), "l"(b));
    return d;
}
__device__ __forceinline__ ull pack2(float x, float y) {
    ull d;
    asm("mov.b64 %0, {%1, %2};" : "=l"(d) : "f"(x), "f"(y));
    return d;
}
__device__ __forceinline__ void unpack2(ull a, float& x, float& y) {
    asm("mov.b64 {%0, %1}, %2;" : "=f"(x), "=f"(y) : "l"(a));
}
__device__ __forceinline__ float tanha(float x) {
    float y;
    asm("tanh.approx.f32 %0, %1;" : "=f"(y) : "f"(x));
    return y;
}
__device__ __forceinline__ void bar_sync(int id) {
    asm volatile("bar.sync %0, %1;" :: "r"(id), "r"(STPB) : "memory");
}

__global__ void __launch_bounds__(TPB, 1)
gru_kernel(const float* __restrict__ noise,
           const float* __restrict__ w_ih,
           const float* __restrict__ w_hh,
           const float* __restrict__ b_ih,
           const float* __restrict__ b_hh,
           float* __restrict__ out)
{
    extern __shared__ __align__(16) char dync[];
    // layout: girz ull[2][CHUNK][H] | gin f32[2][CHUNK][H] | x f32[2][CHUNK*I] | h f32[2][2][H]
    ull*   sh_girz = (ull*)dync;
    float* sh_gin  = (float*)(sh_girz + 2 * CHUNK * H_);
    float* sh_x    = sh_gin + 2 * CHUNK * H_;
    float* sh_hb   = sh_x + 2 * CHUNK * I_;

    const int tid = threadIdx.x;
    const int s   = tid / STPB;     // stream (batch within CTA)
    const int ts  = tid % STPB;
    const int u   = ts >> 1;        // hidden unit 0..63
    const int e   = ts & 1;         // half: k in [32e, 32e+32)
    const int b   = blockIdx.x * 2 + s;
    const int k0  = 32 * e;
    const int BAR = 1 + s;

    ull*   girz = sh_girz + s * CHUNK * H_;
    float* gin  = sh_gin  + s * CHUNK * H_;
    float* xs   = sh_x    + s * CHUNK * I_;
    float* hb   = sh_hb   + s * 2 * H_;

    // W_hh halves, packed by adjacent k-pairs.
    ull whr[16], whz[16], whn[16];
#pragma unroll
    for (int m = 0; m < 16; m++) {
        whr[m] = pack2(w_hh[(0 * H_ + u) * H_ + k0 + 2 * m], w_hh[(0 * H_ + u) * H_ + k0 + 2 * m + 1]);
        whz[m] = pack2(w_hh[(1 * H_ + u) * H_ + k0 + 2 * m], w_hh[(1 * H_ + u) * H_ + k0 + 2 * m + 1]);
        whn[m] = pack2(w_hh[(2 * H_ + u) * H_ + k0 + 2 * m], w_hh[(2 * H_ + u) * H_ + k0 + 2 * m + 1]);
    }
    // W_ih rows: even lane holds r,z; odd lane holds n. Packed by i-pairs.
    ull wi[10];
    float bA = 0.0f, bB = 0.0f;
    if (e == 0) {
#pragma unroll
        for (int p = 0; p < 5; p++) {
            wi[p]     = pack2(w_ih[(0 * H_ + u) * I_ + 2 * p], w_ih[(0 * H_ + u) * I_ + 2 * p + 1]);
            wi[5 + p] = pack2(w_ih[(1 * H_ + u) * I_ + 2 * p], w_ih[(1 * H_ + u) * I_ + 2 * p + 1]);
        }
        bA = b_ih[0 * H_ + u] + b_hh[0 * H_ + u];   // r bias (full)
        bB = b_ih[1 * H_ + u] + b_hh[1 * H_ + u];   // z bias (full)
    } else {
#pragma unroll
        for (int p = 0; p < 5; p++)
            wi[p] = pack2(w_ih[(2 * H_ + u) * I_ + 2 * p], w_ih[(2 * H_ + u) * I_ + 2 * p + 1]);
        bA = b_ih[2 * H_ + u];                      // n input bias
    }
    const float bhn = b_hh[2 * H_ + u];             // n hidden bias (inside r*(.))

    if (ts < H_) hb[ts] = 0.0f;                     // h buffer 0
    float hreg = 0.0f;
    int p = 0;

    const float* xb = noise + (size_t)b * T_ * I_;
    float* op = out + (size_t)b * T_ * H_ + u;
    __syncthreads();

    for (int t0 = 0; t0 < T_; t0 += CHUNK) {
        // Stage x chunk (contiguous).
        for (int idx = ts; idx < CHUNK * I_; idx += STPB)
            xs[idx] = xb[t0 * I_ + idx];
        bar_sync(BAR);

        // Precompute gi for the chunk.
        {
            const ull* xp = (const ull*)xs;
#pragma unroll 2
            for (int tl = 0; tl < CHUNK; tl++) {
                const ull* xt = xp + tl * (I_ / 2);
                if (e == 0) {
                    ull ar = 0ull, az = 0ull;
#pragma unroll
                    for (int q = 0; q < 5; q++) {
                        ull x2 = xt[q];
                        ar = ffma2(x2, wi[q], ar);
                        az = ffma2(x2, wi[5 + q], az);
                    }
                    float rx, ry, zx, zy;
                    unpack2(ar, rx, ry);
                    unpack2(az, zx, zy);
                    girz[tl * H_ + u] = pack2(rx + ry + bA, zx + zy + bB);
                } else {
                    ull an = 0ull;
#pragma unroll
                    for (int q = 0; q < 5; q++)
                        an = ffma2(xt[q], wi[q], an);
                    float nx, ny;
                    unpack2(an, nx, ny);
                    gin[tl * H_ + u] = nx + ny + bA;
                }
            }
        }
        bar_sync(BAR);

        // Recurrent loop: one barrier per step.
        for (int tl = 0; tl < CHUNK; tl++) {
            const ulonglong2* hq = (const ulonglong2*)(hb + p * H_ + k0);
            ull r0 = 0ull, r1 = 0ull, z0 = 0ull, z1 = 0ull, n0 = 0ull, n1 = 0ull;
#pragma unroll
            for (int m = 0; m < 8; m++) {
                ulonglong2 h2 = hq[m];
                r0 = ffma2(h2.x, whr[2 * m], r0);
                z0 = ffma2(h2.x, whz[2 * m], z0);
                n0 = ffma2(h2.x, whn[2 * m], n0);
                r1 = ffma2(h2.y, whr[2 * m + 1], r1);
                z1 = ffma2(h2.y, whz[2 * m + 1], z1);
                n1 = ffma2(h2.y, whn[2 * m + 1], n1);
            }
            float hvr, hvz, hvn;
            {
                float x, y;
                ull t = fadd2(r0, r1); unpack2(t, x, y); hvr = x + y;
                t = fadd2(z0, z1);     unpack2(t, x, y); hvz = x + y;
                t = fadd2(n0, n1);     unpack2(t, x, y); hvn = x + y;
            }
            // Merge the two k-halves (partner lane, same warp).
            hvr += __shfl_xor_sync(0xffffffffu, hvr, 1);
            hvz += __shfl_xor_sync(0xffffffffu, hvz, 1);
            hvn += __shfl_xor_sync(0xffffffffu, hvn, 1);

            float gr, gz;
            unpack2(girz[tl * H_ + u], gr, gz);
            const float gn = gin[tl * H_ + u];

            const float r = fmaf(0.5f, tanha(0.5f * (gr + hvr)), 0.5f);
            const float z = fmaf(0.5f, tanha(0.5f * (gz + hvz)), 0.5f);
            const float n = tanha(fmaf(r, hvn + bhn, gn));
            hreg = fmaf(z, hreg - n, n);            // (1-z)*n + z*h

            if (e == 0) {
                hb[(p ^ 1) * H_ + u] = hreg;
                op[(size_t)(t0 + tl) * H_] = hreg;
            }
            p ^= 1;
            bar_sync(BAR);
        }
    }
}

extern "C" void kernel_launch(void* const* d_in, const int* in_sizes, int n_in,
                              void* d_out, int out_size)
{
    const float* noise = (const float*)d_in[0];
    const float* w_ih  = (const float*)d_in[1];
    const float* w_hh  = (const float*)d_in[2];
    const float* b_ih  = (const float*)d_in[3];
    const float* b_hh  = (const float*)d_in[4];
    float* out = (float*)d_out;

    const int smem = 2 * CHUNK * H_ * 8      // girz (ull)
                   + 2 * CHUNK * H_ * 4      // gin
                   + 2 * CHUNK * I_ * 4      // x
                   + 2 * 2 * H_ * 4;         // h double buffer
    cudaFuncSetAttribute(gru_kernel, cudaFuncAttributeMaxDynamicSharedMemorySize, smem);
    gru_kernel<<<B_ / 2, TPB, smem>>>(noise, w_ih, w_hh, b_ih, b_hh, out);
}